// round 2
// baseline (speedup 1.0000x reference)
#include <cuda_runtime.h>

#define NE 32
#define NH 2048
#define NI 768
#define TWO_I 1536
#define NK 4
#define NT 2048
#define TKP 8192           // T*K pairs (upper bound; duplicates dropped)
#define BM 64
#define BN 64
#define BKD 16
#define MAXTILES 16        // up to 1024 tokens per expert (mean 256)

// ---------------- device scratch (static; no allocations allowed) ------------
__device__ int   g_cnt[NE];
__device__ int   g_off[NE + 1];
__device__ int   g_cur[NE];
__device__ int   g_tok[TKP];
__device__ float g_w[TKP];
__device__ int   g_is64;
__device__ float g_inter[(size_t)TKP * NI];   // weighted silu(gate)*up, expert-grouped

// ---------------- routing build ----------------------------------------------
__global__ void k_init(const int* __restrict__ idx) {
    int t = threadIdx.x;
    if (t < NE) g_cnt[t] = 0;
    if (t == 0) {
        // int64 little-endian with values in [0,32): every high word is 0.
        int ok = 1;
        for (int i = 0; i < 64; i++) {
            if (idx[2 * i + 1] != 0) { ok = 0; break; }
        }
        g_is64 = ok;
    }
}

__device__ __forceinline__ int fetch_idx(const int* __restrict__ idx, int i) {
    return g_is64 ? idx[2 * i] : idx[i];
}

// Reference scatter has last-write-wins semantics: if the same expert appears
// more than once in a token's top-k list, only the LAST occurrence (and its
// weight) counts. Keep pair (t,k) only if expert e does not reappear later.
__device__ __forceinline__ int keep_pair(const int* __restrict__ idx,
                                         int t, int k, int e) {
    for (int k2 = k + 1; k2 < NK; k2++)
        if (fetch_idx(idx, t * NK + k2) == e) return 0;
    return 1;
}

__global__ void k_count(const int* __restrict__ idx) {
    int i = blockIdx.x * blockDim.x + threadIdx.x;
    if (i < TKP) {
        int t = i / NK, k = i % NK;
        int e = fetch_idx(idx, i);
        if (keep_pair(idx, t, k, e)) atomicAdd(&g_cnt[e], 1);
    }
}

__global__ void k_scan() {
    int s = 0;
    for (int e = 0; e < NE; e++) { g_off[e] = s; g_cur[e] = s; s += g_cnt[e]; }
    g_off[NE] = s;
}

__global__ void k_scatter(const int* __restrict__ idx, const float* __restrict__ w) {
    int i = blockIdx.x * blockDim.x + threadIdx.x;
    if (i < TKP) {
        int t = i / NK, k = i % NK;
        int e = fetch_idx(idx, i);
        if (keep_pair(idx, t, k, e)) {
            int pos = atomicAdd(&g_cur[e], 1);
            g_tok[pos] = t;
            g_w[pos]   = w[i];
        }
    }
}

// ---------------- GEMM1: inter = silu(x@Wg) * (x@Wu) * route_w ---------------
__device__ __forceinline__ float silu_f(float v) {
    return v / (1.0f + expf(-v));
}

__global__ __launch_bounds__(256)
void k_gemm1(const float* __restrict__ x, const float* __restrict__ W1) {
    int e = blockIdx.z;
    int start = g_off[e];
    int cnt   = g_off[e + 1] - start;
    int m0 = blockIdx.y * BM;
    if (m0 >= cnt) return;
    int j0 = blockIdx.x * BN;                       // column within [0, NI)
    const float* W = W1 + (size_t)e * NH * TWO_I;

    __shared__ float As[BM][BKD + 4];               // +4 pad kills bank conflicts
    __shared__ float Bg[BKD][BN];
    __shared__ float Bu[BKD][BN];

    int tid = threadIdx.x;
    int tm = (tid >> 4) << 2;                       // 0..60
    int tn = (tid & 15) << 2;                       // 0..60
    int ar = tid >> 2, ac = (tid & 3) << 2;         // A loader: 64 rows x 4-float4
    int br = tid >> 4, bc = (tid & 15) << 2;        // B loader: 16 rows x 16-float4

    const float* xrow = 0;
    if (m0 + ar < cnt) xrow = x + (size_t)g_tok[start + m0 + ar] * NH;

    float accg[4][4] = {}, accu[4][4] = {};

    for (int k0 = 0; k0 < NH; k0 += BKD) {
        float4 av = xrow ? *(const float4*)(xrow + k0 + ac)
                         : make_float4(0.f, 0.f, 0.f, 0.f);
        const float* wrow = W + (size_t)(k0 + br) * TWO_I;
        float4 bgv = *(const float4*)(wrow + j0 + bc);
        float4 buv = *(const float4*)(wrow + NI + j0 + bc);
        __syncthreads();
        *(float4*)&As[ar][ac] = av;
        *(float4*)&Bg[br][bc] = bgv;
        *(float4*)&Bu[br][bc] = buv;
        __syncthreads();
#pragma unroll
        for (int kk = 0; kk < BKD; kk++) {
            float a[4];
#pragma unroll
            for (int r = 0; r < 4; r++) a[r] = As[tm + r][kk];
            float4 bg4 = *(const float4*)&Bg[kk][tn];
            float4 bu4 = *(const float4*)&Bu[kk][tn];
            float bg[4] = {bg4.x, bg4.y, bg4.z, bg4.w};
            float bu[4] = {bu4.x, bu4.y, bu4.z, bu4.w};
#pragma unroll
            for (int r = 0; r < 4; r++) {
#pragma unroll
                for (int c = 0; c < 4; c++) {
                    accg[r][c] += a[r] * bg[c];
                    accu[r][c] += a[r] * bu[c];
                }
            }
        }
    }

#pragma unroll
    for (int r = 0; r < 4; r++) {
        int gm = m0 + tm + r;
        if (gm < cnt) {
            float wv = g_w[start + gm];
            float4 o;
            o.x = silu_f(accg[r][0]) * accu[r][0] * wv;
            o.y = silu_f(accg[r][1]) * accu[r][1] * wv;
            o.z = silu_f(accg[r][2]) * accu[r][2] * wv;
            o.w = silu_f(accg[r][3]) * accu[r][3] * wv;
            *(float4*)&g_inter[(size_t)(start + gm) * NI + j0 + tn] = o;
        }
    }
}

// ---------------- GEMM2: out[t,:] += inter[p,:] @ W2[e]  (atomic combine) ----
__global__ __launch_bounds__(256)
void k_gemm2(const float* __restrict__ W2, float* __restrict__ out) {
    int e = blockIdx.z;
    int start = g_off[e];
    int cnt   = g_off[e + 1] - start;
    int m0 = blockIdx.y * BM;
    if (m0 >= cnt) return;
    int n0 = blockIdx.x * BN;
    const float* W = W2 + (size_t)e * NI * NH;

    __shared__ float As[BM][BKD + 4];
    __shared__ float Bs[BKD][BN];

    int tid = threadIdx.x;
    int tm = (tid >> 4) << 2;
    int tn = (tid & 15) << 2;
    int ar = tid >> 2, ac = (tid & 3) << 2;
    int br = tid >> 4, bc = (tid & 15) << 2;

    const float* arow = 0;
    if (m0 + ar < cnt) arow = g_inter + (size_t)(start + m0 + ar) * NI;

    float acc[4][4] = {};

    for (int k0 = 0; k0 < NI; k0 += BKD) {
        float4 av = arow ? *(const float4*)(arow + k0 + ac)
                         : make_float4(0.f, 0.f, 0.f, 0.f);
        float4 bv = *(const float4*)(W + (size_t)(k0 + br) * NH + n0 + bc);
        __syncthreads();
        *(float4*)&As[ar][ac] = av;
        *(float4*)&Bs[br][bc] = bv;
        __syncthreads();
#pragma unroll
        for (int kk = 0; kk < BKD; kk++) {
            float a[4];
#pragma unroll
            for (int r = 0; r < 4; r++) a[r] = As[tm + r][kk];
            float4 b4 = *(const float4*)&Bs[kk][tn];
            float b[4] = {b4.x, b4.y, b4.z, b4.w};
#pragma unroll
            for (int r = 0; r < 4; r++)
#pragma unroll
                for (int c = 0; c < 4; c++)
                    acc[r][c] += a[r] * b[c];
        }
    }

#pragma unroll
    for (int r = 0; r < 4; r++) {
        int gm = m0 + tm + r;
        if (gm < cnt) {
            int t = g_tok[start + gm];
            float* orow = out + (size_t)t * NH + n0 + tn;
#pragma unroll
            for (int c = 0; c < 4; c++)
                atomicAdd(&orow[c], acc[r][c]);
        }
    }
}

// ---------------- launcher ----------------------------------------------------
extern "C" void kernel_launch(void* const* d_in, const int* in_sizes, int n_in,
                              void* d_out, int out_size) {
    const float* x   = (const float*)d_in[0];
    const int*   idx = (const int*)d_in[1];
    const float* w   = (const float*)d_in[2];
    const float* W1  = (const float*)d_in[3];
    const float* W2  = (const float*)d_in[4];
    float* out = (float*)d_out;

    cudaMemsetAsync(out, 0, (size_t)out_size * sizeof(float));

    k_init<<<1, 64>>>(idx);
    k_count<<<TKP / 256, 256>>>(idx);
    k_scan<<<1, 1>>>();
    k_scatter<<<TKP / 256, 256>>>(idx, w);

    dim3 g1(NI / BN, MAXTILES, NE);
    k_gemm1<<<g1, 256>>>(x, W1);

    dim3 g2(NH / BN, MAXTILES, NE);
    k_gemm2<<<g2, 256>>>(W2, out);
}

// round 3
// speedup vs baseline: 1.0598x; 1.0598x over previous
#include <cuda_runtime.h>

#define NE 32
#define NH 2048
#define NI 768
#define TWO_I 1536
#define NK 4
#define NT 2048
#define TKP 8192
#define BM 64
#define BN 64
#define BKD 16
#define MAXTILES 16

// ---------------- device scratch ---------------------------------------------
__device__ int   g_cnt[NE];
__device__ int   g_off[NE + 1];
__device__ int   g_cur[NE];
__device__ int   g_tok[TKP];
__device__ float g_w[TKP];
__device__ int   g_is64;
__device__ float g_inter[(size_t)TKP * NI];

// ---------------- packed f32x2 helpers (FFMA2 on sm_103a) --------------------
__device__ __forceinline__ unsigned long long bcast2(float a) {
    unsigned long long r;
    unsigned int ai = __float_as_uint(a);
    asm("mov.b64 %0, {%1, %1};" : "=l"(r) : "r"(ai));
    return r;
}
__device__ __forceinline__ void ffma2(unsigned long long& d,
                                      unsigned long long a,
                                      unsigned long long b) {
    asm("fma.rn.f32x2 %0, %1, %2, %0;" : "+l"(d) : "l"(a), "l"(b));
}
__device__ __forceinline__ float2 unpk(unsigned long long v) {
    unsigned int lo, hi;
    asm("mov.b64 {%0, %1}, %2;" : "=r"(lo), "=r"(hi) : "l"(v));
    return make_float2(__uint_as_float(lo), __uint_as_float(hi));
}

// ---------------- routing build ----------------------------------------------
__global__ void k_init(const int* __restrict__ idx) {
    int t = threadIdx.x;
    if (t < NE) g_cnt[t] = 0;
    if (t == 0) {
        int ok = 1;
        for (int i = 0; i < 64; i++) {
            if (idx[2 * i + 1] != 0) { ok = 0; break; }
        }
        g_is64 = ok;
    }
}

__device__ __forceinline__ int fetch_idx(const int* __restrict__ idx, int i) {
    return g_is64 ? idx[2 * i] : idx[i];
}

// Reference scatter is last-write-wins for duplicate experts within a token.
__device__ __forceinline__ int keep_pair(const int* __restrict__ idx,
                                         int t, int k, int e) {
    for (int k2 = k + 1; k2 < NK; k2++)
        if (fetch_idx(idx, t * NK + k2) == e) return 0;
    return 1;
}

__global__ void k_count(const int* __restrict__ idx) {
    int i = blockIdx.x * blockDim.x + threadIdx.x;
    if (i < TKP) {
        int t = i / NK, k = i % NK;
        int e = fetch_idx(idx, i);
        if (keep_pair(idx, t, k, e)) atomicAdd(&g_cnt[e], 1);
    }
}

__global__ void k_scan() {
    int s = 0;
    for (int e = 0; e < NE; e++) { g_off[e] = s; g_cur[e] = s; s += g_cnt[e]; }
    g_off[NE] = s;
}

__global__ void k_scatter(const int* __restrict__ idx, const float* __restrict__ w) {
    int i = blockIdx.x * blockDim.x + threadIdx.x;
    if (i < TKP) {
        int t = i / NK, k = i % NK;
        int e = fetch_idx(idx, i);
        if (keep_pair(idx, t, k, e)) {
            int pos = atomicAdd(&g_cur[e], 1);
            g_tok[pos] = t;
            g_w[pos]   = w[i];
        }
    }
}

// ---------------- GEMM1: inter = silu(x@Wg) * (x@Wu) * route_w ---------------
__device__ __forceinline__ float silu_f(float v) {
    return v / (1.0f + expf(-v));
}

__global__ __launch_bounds__(256)
void k_gemm1(const float* __restrict__ x, const float* __restrict__ W1) {
    int e = blockIdx.z;
    int start = g_off[e];
    int cnt   = g_off[e + 1] - start;
    int m0 = blockIdx.y * BM;
    if (m0 >= cnt) return;
    int j0 = blockIdx.x * BN;
    const float* W = W1 + (size_t)e * NH * TWO_I;

    __shared__ float As[BM][BKD + 4];
    __shared__ float Bg[BKD][BN];
    __shared__ float Bu[BKD][BN];

    int tid = threadIdx.x;
    int tm = (tid >> 4) << 2;
    int tn = (tid & 15) << 2;
    int ar = tid >> 2, ac = (tid & 3) << 2;
    int br = tid >> 4, bc = (tid & 15) << 2;

    const float* xrow = 0;
    if (m0 + ar < cnt) xrow = x + (size_t)g_tok[start + m0 + ar] * NH;

    unsigned long long accg[4][2] = {}, accu[4][2] = {};  // packed f32x2

    for (int k0 = 0; k0 < NH; k0 += BKD) {
        float4 av = xrow ? *(const float4*)(xrow + k0 + ac)
                         : make_float4(0.f, 0.f, 0.f, 0.f);
        const float* wrow = W + (size_t)(k0 + br) * TWO_I;
        float4 bgv = *(const float4*)(wrow + j0 + bc);
        float4 buv = *(const float4*)(wrow + NI + j0 + bc);
        __syncthreads();
        *(float4*)&As[ar][ac] = av;
        *(float4*)&Bg[br][bc] = bgv;
        *(float4*)&Bu[br][bc] = buv;
        __syncthreads();
#pragma unroll
        for (int kk = 0; kk < BKD; kk++) {
            unsigned long long bg01 = *(const unsigned long long*)&Bg[kk][tn];
            unsigned long long bg23 = *(const unsigned long long*)&Bg[kk][tn + 2];
            unsigned long long bu01 = *(const unsigned long long*)&Bu[kk][tn];
            unsigned long long bu23 = *(const unsigned long long*)&Bu[kk][tn + 2];
#pragma unroll
            for (int r = 0; r < 4; r++) {
                unsigned long long aa = bcast2(As[tm + r][kk]);
                ffma2(accg[r][0], aa, bg01);
                ffma2(accg[r][1], aa, bg23);
                ffma2(accu[r][0], aa, bu01);
                ffma2(accu[r][1], aa, bu23);
            }
        }
    }

#pragma unroll
    for (int r = 0; r < 4; r++) {
        int gm = m0 + tm + r;
        if (gm < cnt) {
            float wv = g_w[start + gm];
            float2 g01 = unpk(accg[r][0]), g23 = unpk(accg[r][1]);
            float2 u01 = unpk(accu[r][0]), u23 = unpk(accu[r][1]);
            float4 o;
            o.x = silu_f(g01.x) * u01.x * wv;
            o.y = silu_f(g01.y) * u01.y * wv;
            o.z = silu_f(g23.x) * u23.x * wv;
            o.w = silu_f(g23.y) * u23.y * wv;
            *(float4*)&g_inter[(size_t)(start + gm) * NI + j0 + tn] = o;
        }
    }
}

// ---------------- GEMM2: out[t,:] += inter[p,:] @ W2[e] ----------------------
__global__ __launch_bounds__(256)
void k_gemm2(const float* __restrict__ W2, float* __restrict__ out) {
    int e = blockIdx.z;
    int start = g_off[e];
    int cnt   = g_off[e + 1] - start;
    int m0 = blockIdx.y * BM;
    if (m0 >= cnt) return;
    int n0 = blockIdx.x * BN;
    const float* W = W2 + (size_t)e * NI * NH;

    __shared__ float As[BM][BKD + 4];
    __shared__ float Bs[BKD][BN];

    int tid = threadIdx.x;
    int tm = (tid >> 4) << 2;
    int tn = (tid & 15) << 2;
    int ar = tid >> 2, ac = (tid & 3) << 2;
    int br = tid >> 4, bc = (tid & 15) << 2;

    const float* arow = 0;
    if (m0 + ar < cnt) arow = g_inter + (size_t)(start + m0 + ar) * NI;

    unsigned long long acc[4][2] = {};

    for (int k0 = 0; k0 < NI; k0 += BKD) {
        float4 av = arow ? *(const float4*)(arow + k0 + ac)
                         : make_float4(0.f, 0.f, 0.f, 0.f);
        float4 bv = *(const float4*)(W + (size_t)(k0 + br) * NH + n0 + bc);
        __syncthreads();
        *(float4*)&As[ar][ac] = av;
        *(float4*)&Bs[br][bc] = bv;
        __syncthreads();
#pragma unroll
        for (int kk = 0; kk < BKD; kk++) {
            unsigned long long b01 = *(const unsigned long long*)&Bs[kk][tn];
            unsigned long long b23 = *(const unsigned long long*)&Bs[kk][tn + 2];
#pragma unroll
            for (int r = 0; r < 4; r++) {
                unsigned long long aa = bcast2(As[tm + r][kk]);
                ffma2(acc[r][0], aa, b01);
                ffma2(acc[r][1], aa, b23);
            }
        }
    }

#pragma unroll
    for (int r = 0; r < 4; r++) {
        int gm = m0 + tm + r;
        if (gm < cnt) {
            int t = g_tok[start + gm];
            float* orow = out + (size_t)t * NH + n0 + tn;
            float2 c01 = unpk(acc[r][0]), c23 = unpk(acc[r][1]);
            atomicAdd(&orow[0], c01.x);
            atomicAdd(&orow[1], c01.y);
            atomicAdd(&orow[2], c23.x);
            atomicAdd(&orow[3], c23.y);
        }
    }
}

// ---------------- launcher ----------------------------------------------------
extern "C" void kernel_launch(void* const* d_in, const int* in_sizes, int n_in,
                              void* d_out, int out_size) {
    const float* x   = (const float*)d_in[0];
    const int*   idx = (const int*)d_in[1];
    const float* w   = (const float*)d_in[2];
    const float* W1  = (const float*)d_in[3];
    const float* W2  = (const float*)d_in[4];
    float* out = (float*)d_out;

    cudaMemsetAsync(out, 0, (size_t)out_size * sizeof(float));

    k_init<<<1, 64>>>(idx);
    k_count<<<TKP / 256, 256>>>(idx);
    k_scan<<<1, 1>>>();
    k_scatter<<<TKP / 256, 256>>>(idx, w);

    dim3 g1(NI / BN, MAXTILES, NE);
    k_gemm1<<<g1, 256>>>(x, W1);

    dim3 g2(NH / BN, MAXTILES, NE);
    k_gemm2<<<g2, 256>>>(W2, out);
}

// round 6
// speedup vs baseline: 2.2799x; 2.1513x over previous
#include <cuda_runtime.h>
#include <cuda_bf16.h>
#include <cstdint>

#define NE 32
#define NH 2048
#define NI 768
#define TWO_I 1536
#define NK 4
#define TKP 8192
#define PADS 12288
#define MAXTT 128
#define BM 128
#define KC 32
#define ASTR 40      // A smem row stride (bf16 elems): 32 + 8 pad
#define BSTR 72      // B smem row stride (bf16 elems): 64 + 8 pad

// ---------------- device scratch ---------------------------------------------
__device__ int   g_tok[PADS];
__device__ float g_w[PADS];
__device__ int   g_tile_e[MAXTT];
__device__ int   g_tile_base[MAXTT];
__device__ __nv_bfloat16 g_ih[(size_t)PADS * NI];
__device__ __nv_bfloat16 g_il[(size_t)PADS * NI];

// ---------------- helpers -----------------------------------------------------
__device__ __forceinline__ uint32_t smem_u32(const void* p) {
    uint32_t a;
    asm("{ .reg .u64 t; cvta.to.shared.u64 t, %1; cvt.u32.u64 %0, t; }" : "=r"(a) : "l"(p));
    return a;
}
__device__ __forceinline__ void ldm_x4(uint32_t* r, uint32_t addr) {
    asm volatile("ldmatrix.sync.aligned.m8n8.x4.shared.b16 {%0,%1,%2,%3}, [%4];"
        : "=r"(r[0]), "=r"(r[1]), "=r"(r[2]), "=r"(r[3]) : "r"(addr));
}
__device__ __forceinline__ void ldm_x4t(uint32_t* r, uint32_t addr) {
    asm volatile("ldmatrix.sync.aligned.m8n8.x4.trans.shared.b16 {%0,%1,%2,%3}, [%4];"
        : "=r"(r[0]), "=r"(r[1]), "=r"(r[2]), "=r"(r[3]) : "r"(addr));
}
__device__ __forceinline__ void mma_bf16(float* d, const uint32_t* a, const uint32_t* b) {
    asm volatile("mma.sync.aligned.m16n8k16.row.col.f32.bf16.bf16.f32 "
        "{%0,%1,%2,%3}, {%4,%5,%6,%7}, {%8,%9}, {%0,%1,%2,%3};"
        : "+f"(d[0]), "+f"(d[1]), "+f"(d[2]), "+f"(d[3])
        : "r"(a[0]), "r"(a[1]), "r"(a[2]), "r"(a[3]), "r"(b[0]), "r"(b[1]));
}
__device__ __forceinline__ void split2(float f0, float f1, uint32_t& h, uint32_t& l) {
    __nv_bfloat162 hb = __floats2bfloat162_rn(f0, f1);
    float2 hf = __bfloat1622float2(hb);
    __nv_bfloat162 lb = __floats2bfloat162_rn(f0 - hf.x, f1 - hf.y);
    h = *reinterpret_cast<uint32_t*>(&hb);
    l = *reinterpret_cast<uint32_t*>(&lb);
}
__device__ __forceinline__ float silu_f(float v) { return v / (1.0f + expf(-v)); }

// ---------------- routing -----------------------------------------------------
__global__ void k_route(const int* __restrict__ idx, const float* __restrict__ wgt) {
    __shared__ int s_cnt[NE], s_pb[NE], s_cur[NE], s_pe[NE];
    __shared__ int s_is64;
    int tid = threadIdx.x;
    if (tid < NE) s_cnt[tid] = 0;
    if (tid == 0) {
        int ok = 1;
        for (int i = 0; i < 64; i++) if (idx[2 * i + 1] != 0) { ok = 0; break; }
        s_is64 = ok;
    }
    __syncthreads();
    int is64 = s_is64;
    for (int i = tid; i < TKP; i += blockDim.x) {
        int t = i / NK, k = i % NK;
        int e = is64 ? idx[2 * i] : idx[i];
        int keep = 1;
        for (int k2 = k + 1; k2 < NK; k2++) {
            int e2 = is64 ? idx[2 * (t * NK + k2)] : idx[t * NK + k2];
            if (e2 == e) { keep = 0; break; }
        }
        if (keep) atomicAdd(&s_cnt[e], 1);
    }
    __syncthreads();
    if (tid == 0) {
        int pb = 0, tl = 0;
        for (int e = 0; e < NE; e++) {
            s_pb[e] = pb; s_cur[e] = pb;
            int nt = (s_cnt[e] + BM - 1) / BM;
            for (int j = 0; j < nt; j++) { g_tile_e[tl] = e; g_tile_base[tl] = pb + j * BM; tl++; }
            pb += nt * BM;
            s_pe[e] = pb;
        }
        for (int t2 = tl; t2 < MAXTT; t2++) g_tile_e[t2] = -1;
    }
    __syncthreads();
    for (int i = tid; i < TKP; i += blockDim.x) {
        int t = i / NK, k = i % NK;
        int e = is64 ? idx[2 * i] : idx[i];
        int keep = 1;
        for (int k2 = k + 1; k2 < NK; k2++) {
            int e2 = is64 ? idx[2 * (t * NK + k2)] : idx[t * NK + k2];
            if (e2 == e) { keep = 0; break; }
        }
        if (keep) {
            int pos = atomicAdd(&s_cur[e], 1);
            g_tok[pos] = t; g_w[pos] = wgt[i];
        }
    }
    __syncthreads();
    for (int e = 0; e < NE; e++)
        for (int i = s_pb[e] + s_cnt[e] + tid; i < s_pe[e]; i += blockDim.x) {
            g_tok[i] = 0; g_w[i] = 0.f;
        }
}

// ---------------- GEMM1: inter = silu(x@Wg)*(x@Wu)*w (bf16 hi/lo out) ---------
__global__ __launch_bounds__(256)
void k_gemm1(const float* __restrict__ x, const float* __restrict__ W1) {
    int tile = blockIdx.y;
    int e = g_tile_e[tile];
    if (e < 0) return;
    int base = g_tile_base[tile];
    int j0 = blockIdx.x * 64;

    __shared__ __align__(16) __nv_bfloat16 Ah[BM * ASTR], Al[BM * ASTR];
    __shared__ __align__(16) __nv_bfloat16 Bgh[KC * BSTR], Bgl[KC * BSTR];
    __shared__ __align__(16) __nv_bfloat16 Buh[KC * BSTR], Bul[KC * BSTR];

    int tid = threadIdx.x, lane = tid & 31, wid = tid >> 5;
    int wm = wid & 3, wn = wid >> 2;

    const float* W = W1 + (size_t)e * NH * TWO_I;

    int arow = tid >> 1, akp = (tid & 1) * 16;
    const float* xrow = x + (size_t)g_tok[base + arow] * NH + akp;
    int bkr = tid >> 3, bc = (tid & 7) * 8;

    uint32_t sAh = smem_u32(Ah), sAl = smem_u32(Al);
    uint32_t sBgh = smem_u32(Bgh), sBgl = smem_u32(Bgl);
    uint32_t sBuh = smem_u32(Buh), sBul = smem_u32(Bul);

    // ldmatrix per-lane byte offsets
    uint32_t aoff[2], boff[2];
#pragma unroll
    for (int mf = 0; mf < 2; mf++)
        aoff[mf] = (uint32_t)((wm * 32 + mf * 16 + (lane & 15)) * (ASTR * 2) + (lane >> 4) * 16);
#pragma unroll
    for (int nb = 0; nb < 2; nb++)
        boff[nb] = (uint32_t)((lane & 15) * (BSTR * 2) + (wn * 32 + nb * 16 + (lane >> 4) * 8) * 2);

    float accg[2][4][4] = {}, accu[2][4][4] = {};

    for (int c = 0; c < NH / KC; c++) {
        int k0 = c * KC;
        // ---- load + split A (gathered tokens) ----
        {
            const float4* px = (const float4*)(xrow + k0);
            float4 v0 = px[0], v1 = px[1], v2 = px[2], v3 = px[3];
            int o = arow * ASTR + akp;
            uint32_t h, l;
            split2(v0.x, v0.y, h, l); *(uint32_t*)&Ah[o + 0]  = h; *(uint32_t*)&Al[o + 0]  = l;
            split2(v0.z, v0.w, h, l); *(uint32_t*)&Ah[o + 2]  = h; *(uint32_t*)&Al[o + 2]  = l;
            split2(v1.x, v1.y, h, l); *(uint32_t*)&Ah[o + 4]  = h; *(uint32_t*)&Al[o + 4]  = l;
            split2(v1.z, v1.w, h, l); *(uint32_t*)&Ah[o + 6]  = h; *(uint32_t*)&Al[o + 6]  = l;
            split2(v2.x, v2.y, h, l); *(uint32_t*)&Ah[o + 8]  = h; *(uint32_t*)&Al[o + 8]  = l;
            split2(v2.z, v2.w, h, l); *(uint32_t*)&Ah[o + 10] = h; *(uint32_t*)&Al[o + 10] = l;
            split2(v3.x, v3.y, h, l); *(uint32_t*)&Ah[o + 12] = h; *(uint32_t*)&Al[o + 12] = l;
            split2(v3.z, v3.w, h, l); *(uint32_t*)&Ah[o + 14] = h; *(uint32_t*)&Al[o + 14] = l;
        }
        // ---- load + split B (gate + up), smem [k][n] ----
        {
            const float* pg = W + (size_t)(k0 + bkr) * TWO_I + j0 + bc;
            float4 gg0 = *(const float4*)pg,        gg1 = *(const float4*)(pg + 4);
            float4 uu0 = *(const float4*)(pg + NI), uu1 = *(const float4*)(pg + NI + 4);
            int o = bkr * BSTR + bc;
            uint32_t h, l;
            split2(gg0.x, gg0.y, h, l); *(uint32_t*)&Bgh[o + 0] = h; *(uint32_t*)&Bgl[o + 0] = l;
            split2(gg0.z, gg0.w, h, l); *(uint32_t*)&Bgh[o + 2] = h; *(uint32_t*)&Bgl[o + 2] = l;
            split2(gg1.x, gg1.y, h, l); *(uint32_t*)&Bgh[o + 4] = h; *(uint32_t*)&Bgl[o + 4] = l;
            split2(gg1.z, gg1.w, h, l); *(uint32_t*)&Bgh[o + 6] = h; *(uint32_t*)&Bgl[o + 6] = l;
            split2(uu0.x, uu0.y, h, l); *(uint32_t*)&Buh[o + 0] = h; *(uint32_t*)&Bul[o + 0] = l;
            split2(uu0.z, uu0.w, h, l); *(uint32_t*)&Buh[o + 2] = h; *(uint32_t*)&Bul[o + 2] = l;
            split2(uu1.x, uu1.y, h, l); *(uint32_t*)&Buh[o + 4] = h; *(uint32_t*)&Bul[o + 4] = l;
            split2(uu1.z, uu1.w, h, l); *(uint32_t*)&Buh[o + 6] = h; *(uint32_t*)&Bul[o + 6] = l;
        }
        __syncthreads();
#pragma unroll
        for (int s = 0; s < 2; s++) {
            uint32_t ah[2][4], al[2][4], bg[2][4], bu[2][4];
            uint32_t as_ = (uint32_t)(s * 32), bs_ = (uint32_t)(s * 16 * BSTR * 2);
            ldm_x4(ah[0], sAh + aoff[0] + as_);
            ldm_x4(ah[1], sAh + aoff[1] + as_);
            ldm_x4(al[0], sAl + aoff[0] + as_);
            ldm_x4(al[1], sAl + aoff[1] + as_);
            ldm_x4t(bg[0], sBgh + boff[0] + bs_);
            ldm_x4t(bg[1], sBgh + boff[1] + bs_);
            ldm_x4t(bu[0], sBuh + boff[0] + bs_);
            ldm_x4t(bu[1], sBuh + boff[1] + bs_);
#pragma unroll
            for (int mf = 0; mf < 2; mf++)
#pragma unroll
                for (int nb = 0; nb < 2; nb++)
#pragma unroll
                    for (int f = 0; f < 2; f++) {
                        mma_bf16(accg[mf][nb * 2 + f], ah[mf], &bg[nb][f * 2]);
                        mma_bf16(accu[mf][nb * 2 + f], ah[mf], &bu[nb][f * 2]);
                        mma_bf16(accg[mf][nb * 2 + f], al[mf], &bg[nb][f * 2]);
                        mma_bf16(accu[mf][nb * 2 + f], al[mf], &bu[nb][f * 2]);
                    }
            ldm_x4t(bg[0], sBgl + boff[0] + bs_);
            ldm_x4t(bg[1], sBgl + boff[1] + bs_);
            ldm_x4t(bu[0], sBul + boff[0] + bs_);
            ldm_x4t(bu[1], sBul + boff[1] + bs_);
#pragma unroll
            for (int mf = 0; mf < 2; mf++)
#pragma unroll
                for (int nb = 0; nb < 2; nb++)
#pragma unroll
                    for (int f = 0; f < 2; f++) {
                        mma_bf16(accg[mf][nb * 2 + f], ah[mf], &bg[nb][f * 2]);
                        mma_bf16(accu[mf][nb * 2 + f], ah[mf], &bu[nb][f * 2]);
                    }
        }
        __syncthreads();
    }

    // ---- epilogue: silu(gate)*up*w -> bf16 hi/lo intermediate ----
#pragma unroll
    for (int mf = 0; mf < 2; mf++) {
        int rA = base + wm * 32 + mf * 16 + (lane >> 2);
        float wa = g_w[rA], wb = g_w[rA + 8];
#pragma unroll
        for (int nf = 0; nf < 4; nf++) {
            int col = j0 + wn * 32 + nf * 8 + (lane & 3) * 2;
            float o0 = silu_f(accg[mf][nf][0]) * accu[mf][nf][0] * wa;
            float o1 = silu_f(accg[mf][nf][1]) * accu[mf][nf][1] * wa;
            float o2 = silu_f(accg[mf][nf][2]) * accu[mf][nf][2] * wb;
            float o3 = silu_f(accg[mf][nf][3]) * accu[mf][nf][3] * wb;
            uint32_t h, l;
            split2(o0, o1, h, l);
            *(uint32_t*)&g_ih[(size_t)rA * NI + col] = h;
            *(uint32_t*)&g_il[(size_t)rA * NI + col] = l;
            split2(o2, o3, h, l);
            *(uint32_t*)&g_ih[(size_t)(rA + 8) * NI + col] = h;
            *(uint32_t*)&g_il[(size_t)(rA + 8) * NI + col] = l;
        }
    }
}

// ---------------- GEMM2: out[t,:] += inter @ W2[e] ----------------------------
__global__ __launch_bounds__(256)
void k_gemm2(const float* __restrict__ W2, float* __restrict__ out) {
    int tile = blockIdx.y;
    int e = g_tile_e[tile];
    if (e < 0) return;
    int base = g_tile_base[tile];
    int n0 = blockIdx.x * 64;

    __shared__ __align__(16) __nv_bfloat16 Ah[BM * ASTR], Al[BM * ASTR];
    __shared__ __align__(16) __nv_bfloat16 Bh[KC * BSTR], Bl[KC * BSTR];

    int tid = threadIdx.x, lane = tid & 31, wid = tid >> 5;
    int wm = wid & 3, wn = wid >> 2;

    const float* W = W2 + (size_t)e * NI * NH;

    int arow = tid >> 1, akp = (tid & 1) * 16;
    const __nv_bfloat16* ih = g_ih + (size_t)(base + arow) * NI + akp;
    const __nv_bfloat16* il = g_il + (size_t)(base + arow) * NI + akp;
    int bkr = tid >> 3, bc = (tid & 7) * 8;

    uint32_t sAh = smem_u32(Ah), sAl = smem_u32(Al);
    uint32_t sBh = smem_u32(Bh), sBl = smem_u32(Bl);

    uint32_t aoff[2], boff[2];
#pragma unroll
    for (int mf = 0; mf < 2; mf++)
        aoff[mf] = (uint32_t)((wm * 32 + mf * 16 + (lane & 15)) * (ASTR * 2) + (lane >> 4) * 16);
#pragma unroll
    for (int nb = 0; nb < 2; nb++)
        boff[nb] = (uint32_t)((lane & 15) * (BSTR * 2) + (wn * 32 + nb * 16 + (lane >> 4) * 8) * 2);

    float acc[2][4][4] = {};

    for (int c = 0; c < NI / KC; c++) {
        int k0 = c * KC;
        {
            // FIX R5: each thread owns 16 bf16 per chunk, load TWO uint4 (was one)
            const uint4* ph = (const uint4*)(ih + k0);
            const uint4* pl = (const uint4*)(il + k0);
            uint4 vh0 = ph[0], vh1 = ph[1];
            uint4 vl0 = pl[0], vl1 = pl[1];
            int o = arow * ASTR + akp;
            *(uint4*)&Ah[o]     = vh0;
            *(uint4*)&Ah[o + 8] = vh1;
            *(uint4*)&Al[o]     = vl0;
            *(uint4*)&Al[o + 8] = vl1;
        }
        {
            const float* pb = W + (size_t)(k0 + bkr) * NH + n0 + bc;
            float4 b0 = *(const float4*)pb, b1 = *(const float4*)(pb + 4);
            int o = bkr * BSTR + bc;
            uint32_t h, l;
            split2(b0.x, b0.y, h, l); *(uint32_t*)&Bh[o + 0] = h; *(uint32_t*)&Bl[o + 0] = l;
            split2(b0.z, b0.w, h, l); *(uint32_t*)&Bh[o + 2] = h; *(uint32_t*)&Bl[o + 2] = l;
            split2(b1.x, b1.y, h, l); *(uint32_t*)&Bh[o + 4] = h; *(uint32_t*)&Bl[o + 4] = l;
            split2(b1.z, b1.w, h, l); *(uint32_t*)&Bh[o + 6] = h; *(uint32_t*)&Bl[o + 6] = l;
        }
        __syncthreads();
#pragma unroll
        for (int s = 0; s < 2; s++) {
            uint32_t ah[2][4], al[2][4], bb[2][4];
            uint32_t as_ = (uint32_t)(s * 32), bs_ = (uint32_t)(s * 16 * BSTR * 2);
            ldm_x4(ah[0], sAh + aoff[0] + as_);
            ldm_x4(ah[1], sAh + aoff[1] + as_);
            ldm_x4(al[0], sAl + aoff[0] + as_);
            ldm_x4(al[1], sAl + aoff[1] + as_);
            ldm_x4t(bb[0], sBh + boff[0] + bs_);
            ldm_x4t(bb[1], sBh + boff[1] + bs_);
#pragma unroll
            for (int mf = 0; mf < 2; mf++)
#pragma unroll
                for (int nb = 0; nb < 2; nb++)
#pragma unroll
                    for (int f = 0; f < 2; f++) {
                        mma_bf16(acc[mf][nb * 2 + f], ah[mf], &bb[nb][f * 2]);
                        mma_bf16(acc[mf][nb * 2 + f], al[mf], &bb[nb][f * 2]);
                    }
            ldm_x4t(bb[0], sBl + boff[0] + bs_);
            ldm_x4t(bb[1], sBl + boff[1] + bs_);
#pragma unroll
            for (int mf = 0; mf < 2; mf++)
#pragma unroll
                for (int nb = 0; nb < 2; nb++)
#pragma unroll
                    for (int f = 0; f < 2; f++)
                        mma_bf16(acc[mf][nb * 2 + f], ah[mf], &bb[nb][f * 2]);
        }
        __syncthreads();
    }

#pragma unroll
    for (int mf = 0; mf < 2; mf++) {
        int rA = base + wm * 32 + mf * 16 + (lane >> 2);
        int tA = g_tok[rA], tB = g_tok[rA + 8];
#pragma unroll
        for (int nf = 0; nf < 4; nf++) {
            int col = n0 + wn * 32 + nf * 8 + (lane & 3) * 2;
            atomicAdd(&out[(size_t)tA * NH + col],     acc[mf][nf][0]);
            atomicAdd(&out[(size_t)tA * NH + col + 1], acc[mf][nf][1]);
            atomicAdd(&out[(size_t)tB * NH + col],     acc[mf][nf][2]);
            atomicAdd(&out[(size_t)tB * NH + col + 1], acc[mf][nf][3]);
        }
    }
}

// ---------------- launcher ----------------------------------------------------
extern "C" void kernel_launch(void* const* d_in, const int* in_sizes, int n_in,
                              void* d_out, int out_size) {
    const float* x   = (const float*)d_in[0];
    const int*   idx = (const int*)d_in[1];
    const float* w   = (const float*)d_in[2];
    const float* W1  = (const float*)d_in[3];
    const float* W2  = (const float*)d_in[4];
    float* out = (float*)d_out;

    cudaMemsetAsync(out, 0, (size_t)out_size * sizeof(float));
    k_route<<<1, 256>>>(idx, w);

    dim3 g1(NI / 64, MAXTT);       // 12 x 128
    k_gemm1<<<g1, 256>>>(x, W1);

    dim3 g2(NH / 64, MAXTT);       // 32 x 128
    k_gemm2<<<g2, 256>>>(W2, out);
}

// round 7
// speedup vs baseline: 2.3281x; 1.0212x over previous
#include <cuda_runtime.h>
#include <cuda_bf16.h>
#include <cstdint>

#define NE 32
#define NH 2048
#define NI 768
#define TWO_I 1536
#define NK 4
#define TKP 8192
#define PADS 12288
#define MAXTT 128
#define BM 128
#define KC 32
#define ASTR 40      // A smem row stride (bf16 elems): 32 + 8 pad
#define BSTR 72      // B smem row stride (bf16 elems): 64 + 8 pad

// ---------------- device scratch ---------------------------------------------
__device__ int   g_cnt[NE];
__device__ int   g_off[NE + 1];
__device__ int   g_cur[NE];
__device__ int   g_tok[PADS];
__device__ float g_w[PADS];
__device__ int   g_is64;
__device__ int   g_tile_e[MAXTT];
__device__ int   g_tile_base[MAXTT];
__device__ __nv_bfloat16 g_ih[(size_t)PADS * NI];
__device__ __nv_bfloat16 g_il[(size_t)PADS * NI];

// ---------------- helpers -----------------------------------------------------
__device__ __forceinline__ uint32_t smem_u32(const void* p) {
    uint32_t a;
    asm("{ .reg .u64 t; cvta.to.shared.u64 t, %1; cvt.u32.u64 %0, t; }" : "=r"(a) : "l"(p));
    return a;
}
__device__ __forceinline__ void ldm_x4(uint32_t* r, uint32_t addr) {
    asm volatile("ldmatrix.sync.aligned.m8n8.x4.shared.b16 {%0,%1,%2,%3}, [%4];"
        : "=r"(r[0]), "=r"(r[1]), "=r"(r[2]), "=r"(r[3]) : "r"(addr));
}
__device__ __forceinline__ void ldm_x4t(uint32_t* r, uint32_t addr) {
    asm volatile("ldmatrix.sync.aligned.m8n8.x4.trans.shared.b16 {%0,%1,%2,%3}, [%4];"
        : "=r"(r[0]), "=r"(r[1]), "=r"(r[2]), "=r"(r[3]) : "r"(addr));
}
__device__ __forceinline__ void mma_bf16(float* d, const uint32_t* a, const uint32_t* b) {
    asm volatile("mma.sync.aligned.m16n8k16.row.col.f32.bf16.bf16.f32 "
        "{%0,%1,%2,%3}, {%4,%5,%6,%7}, {%8,%9}, {%0,%1,%2,%3};"
        : "+f"(d[0]), "+f"(d[1]), "+f"(d[2]), "+f"(d[3])
        : "r"(a[0]), "r"(a[1]), "r"(a[2]), "r"(a[3]), "r"(b[0]), "r"(b[1]));
}
__device__ __forceinline__ void split2(float f0, float f1, uint32_t& h, uint32_t& l) {
    __nv_bfloat162 hb = __floats2bfloat162_rn(f0, f1);
    float2 hf = __bfloat1622float2(hb);
    __nv_bfloat162 lb = __floats2bfloat162_rn(f0 - hf.x, f1 - hf.y);
    h = *reinterpret_cast<uint32_t*>(&hb);
    l = *reinterpret_cast<uint32_t*>(&lb);
}
__device__ __forceinline__ float silu_f(float v) { return v / (1.0f + expf(-v)); }

__device__ __forceinline__ int fetch_idx(const int* __restrict__ idx, int i, int is64) {
    return is64 ? idx[2 * i] : idx[i];
}
__device__ __forceinline__ int keep_pair(const int* __restrict__ idx, int t, int k,
                                         int e, int is64) {
    for (int k2 = k + 1; k2 < NK; k2++)
        if (fetch_idx(idx, t * NK + k2, is64) == e) return 0;
    return 1;
}

// ---------------- routing (parallel) ------------------------------------------
__global__ void k_init(const int* __restrict__ idx) {
    if (threadIdx.x < NE) g_cnt[threadIdx.x] = 0;
    if (threadIdx.x == 0) {
        int ok = 1;
        for (int i = 0; i < 64; i++) if (idx[2 * i + 1] != 0) { ok = 0; break; }
        g_is64 = ok;
    }
}
__global__ void k_fill() {
    int i = blockIdx.x * blockDim.x + threadIdx.x;
    if (i < PADS) { g_tok[i] = 0; g_w[i] = 0.f; }
}
__global__ void k_count(const int* __restrict__ idx) {
    int i = blockIdx.x * blockDim.x + threadIdx.x;
    if (i < TKP) {
        int is64 = g_is64;
        int t = i / NK, k = i % NK;
        int e = fetch_idx(idx, i, is64);
        if (keep_pair(idx, t, k, e, is64)) atomicAdd(&g_cnt[e], 1);
    }
}
__global__ void k_scan() {
    int pb = 0, tl = 0;
    for (int e = 0; e < NE; e++) {
        g_off[e] = pb; g_cur[e] = pb;
        int nt = (g_cnt[e] + BM - 1) / BM;
        for (int j = 0; j < nt; j++) { g_tile_e[tl] = e; g_tile_base[tl] = pb + j * BM; tl++; }
        pb += nt * BM;
    }
    g_off[NE] = pb;
    for (int t2 = tl; t2 < MAXTT; t2++) g_tile_e[t2] = -1;
}
__global__ void k_scatter(const int* __restrict__ idx, const float* __restrict__ wgt) {
    int i = blockIdx.x * blockDim.x + threadIdx.x;
    if (i < TKP) {
        int is64 = g_is64;
        int t = i / NK, k = i % NK;
        int e = fetch_idx(idx, i, is64);
        if (keep_pair(idx, t, k, e, is64)) {
            int pos = atomicAdd(&g_cur[e], 1);
            g_tok[pos] = t; g_w[pos] = wgt[i];
        }
    }
}

// ---------------- GEMM1: inter = silu(x@Wg)*(x@Wu)*w (bf16 hi/lo out) ---------
__global__ __launch_bounds__(256)
void k_gemm1(const float* __restrict__ x, const float* __restrict__ W1) {
    int tile = blockIdx.y;
    int e = g_tile_e[tile];
    if (e < 0) return;
    int base = g_tile_base[tile];
    int j0 = blockIdx.x * 64;

    __shared__ __align__(16) __nv_bfloat16 Ah[BM * ASTR], Al[BM * ASTR];
    __shared__ __align__(16) __nv_bfloat16 Bgh[KC * BSTR], Bgl[KC * BSTR];
    __shared__ __align__(16) __nv_bfloat16 Buh[KC * BSTR], Bul[KC * BSTR];

    int tid = threadIdx.x, lane = tid & 31, wid = tid >> 5;
    int wm = wid & 3, wn = wid >> 2;

    const float* W = W1 + (size_t)e * NH * TWO_I;

    int arow = tid >> 1, akp = (tid & 1) * 16;
    const float* xrow = x + (size_t)g_tok[base + arow] * NH + akp;
    int bkr = tid >> 3, bc = (tid & 7) * 8;
    const float* wbase = W + (size_t)bkr * TWO_I + j0 + bc;
    int oA = arow * ASTR + akp;
    int oB = bkr * BSTR + bc;

    uint32_t sAh = smem_u32(Ah), sAl = smem_u32(Al);
    uint32_t sBgh = smem_u32(Bgh), sBgl = smem_u32(Bgl);
    uint32_t sBuh = smem_u32(Buh), sBul = smem_u32(Bul);

    uint32_t aoff[2], boff[2];
#pragma unroll
    for (int mf = 0; mf < 2; mf++)
        aoff[mf] = (uint32_t)((wm * 32 + mf * 16 + (lane & 15)) * (ASTR * 2) + (lane >> 4) * 16);
#pragma unroll
    for (int nb = 0; nb < 2; nb++)
        boff[nb] = (uint32_t)((lane & 15) * (BSTR * 2) + (wn * 32 + nb * 16 + (lane >> 4) * 8) * 2);

    float accg[2][4][4] = {}, accu[2][4][4] = {};

    const int NC = NH / KC;

    // ---- prologue: load + store chunk 0 ----
    {
        const float4* px = (const float4*)xrow;
        float4 a0 = px[0], a1 = px[1], a2 = px[2], a3 = px[3];
        float4 gg0 = *(const float4*)wbase,        gg1 = *(const float4*)(wbase + 4);
        float4 uu0 = *(const float4*)(wbase + NI), uu1 = *(const float4*)(wbase + NI + 4);
        uint32_t h, l;
        split2(a0.x, a0.y, h, l); *(uint32_t*)&Ah[oA + 0]  = h; *(uint32_t*)&Al[oA + 0]  = l;
        split2(a0.z, a0.w, h, l); *(uint32_t*)&Ah[oA + 2]  = h; *(uint32_t*)&Al[oA + 2]  = l;
        split2(a1.x, a1.y, h, l); *(uint32_t*)&Ah[oA + 4]  = h; *(uint32_t*)&Al[oA + 4]  = l;
        split2(a1.z, a1.w, h, l); *(uint32_t*)&Ah[oA + 6]  = h; *(uint32_t*)&Al[oA + 6]  = l;
        split2(a2.x, a2.y, h, l); *(uint32_t*)&Ah[oA + 8]  = h; *(uint32_t*)&Al[oA + 8]  = l;
        split2(a2.z, a2.w, h, l); *(uint32_t*)&Ah[oA + 10] = h; *(uint32_t*)&Al[oA + 10] = l;
        split2(a3.x, a3.y, h, l); *(uint32_t*)&Ah[oA + 12] = h; *(uint32_t*)&Al[oA + 12] = l;
        split2(a3.z, a3.w, h, l); *(uint32_t*)&Ah[oA + 14] = h; *(uint32_t*)&Al[oA + 14] = l;
        split2(gg0.x, gg0.y, h, l); *(uint32_t*)&Bgh[oB + 0] = h; *(uint32_t*)&Bgl[oB + 0] = l;
        split2(gg0.z, gg0.w, h, l); *(uint32_t*)&Bgh[oB + 2] = h; *(uint32_t*)&Bgl[oB + 2] = l;
        split2(gg1.x, gg1.y, h, l); *(uint32_t*)&Bgh[oB + 4] = h; *(uint32_t*)&Bgl[oB + 4] = l;
        split2(gg1.z, gg1.w, h, l); *(uint32_t*)&Bgh[oB + 6] = h; *(uint32_t*)&Bgl[oB + 6] = l;
        split2(uu0.x, uu0.y, h, l); *(uint32_t*)&Buh[oB + 0] = h; *(uint32_t*)&Bul[oB + 0] = l;
        split2(uu0.z, uu0.w, h, l); *(uint32_t*)&Buh[oB + 2] = h; *(uint32_t*)&Bul[oB + 2] = l;
        split2(uu1.x, uu1.y, h, l); *(uint32_t*)&Buh[oB + 4] = h; *(uint32_t*)&Bul[oB + 4] = l;
        split2(uu1.z, uu1.w, h, l); *(uint32_t*)&Buh[oB + 6] = h; *(uint32_t*)&Bul[oB + 6] = l;
    }
    __syncthreads();

    for (int c = 0; c < NC; c++) {
        // ---- prefetch chunk c+1 into registers (LDG in flight over compute) ----
        float4 a0, a1, a2, a3, gg0, gg1, uu0, uu1;
        bool more = (c + 1 < NC);
        if (more) {
            int k0 = (c + 1) * KC;
            const float4* px = (const float4*)(xrow + k0);
            a0 = px[0]; a1 = px[1]; a2 = px[2]; a3 = px[3];
            const float* pg = wbase + (size_t)k0 * TWO_I;
            gg0 = *(const float4*)pg;        gg1 = *(const float4*)(pg + 4);
            uu0 = *(const float4*)(pg + NI); uu1 = *(const float4*)(pg + NI + 4);
        }
        // ---- compute chunk c from smem ----
#pragma unroll
        for (int s = 0; s < 2; s++) {
            uint32_t ah[2][4], al[2][4], bg[2][4], bu[2][4];
            uint32_t as_ = (uint32_t)(s * 32), bs_ = (uint32_t)(s * 16 * BSTR * 2);
            ldm_x4(ah[0], sAh + aoff[0] + as_);
            ldm_x4(ah[1], sAh + aoff[1] + as_);
            ldm_x4(al[0], sAl + aoff[0] + as_);
            ldm_x4(al[1], sAl + aoff[1] + as_);
            ldm_x4t(bg[0], sBgh + boff[0] + bs_);
            ldm_x4t(bg[1], sBgh + boff[1] + bs_);
            ldm_x4t(bu[0], sBuh + boff[0] + bs_);
            ldm_x4t(bu[1], sBuh + boff[1] + bs_);
#pragma unroll
            for (int mf = 0; mf < 2; mf++)
#pragma unroll
                for (int nb = 0; nb < 2; nb++)
#pragma unroll
                    for (int f = 0; f < 2; f++) {
                        mma_bf16(accg[mf][nb * 2 + f], ah[mf], &bg[nb][f * 2]);
                        mma_bf16(accu[mf][nb * 2 + f], ah[mf], &bu[nb][f * 2]);
                        mma_bf16(accg[mf][nb * 2 + f], al[mf], &bg[nb][f * 2]);
                        mma_bf16(accu[mf][nb * 2 + f], al[mf], &bu[nb][f * 2]);
                    }
            ldm_x4t(bg[0], sBgl + boff[0] + bs_);
            ldm_x4t(bg[1], sBgl + boff[1] + bs_);
            ldm_x4t(bu[0], sBul + boff[0] + bs_);
            ldm_x4t(bu[1], sBul + boff[1] + bs_);
#pragma unroll
            for (int mf = 0; mf < 2; mf++)
#pragma unroll
                for (int nb = 0; nb < 2; nb++)
#pragma unroll
                    for (int f = 0; f < 2; f++) {
                        mma_bf16(accg[mf][nb * 2 + f], ah[mf], &bg[nb][f * 2]);
                        mma_bf16(accu[mf][nb * 2 + f], ah[mf], &bu[nb][f * 2]);
                    }
        }
        __syncthreads();
        // ---- store prefetched chunk ----
        if (more) {
            uint32_t h, l;
            split2(a0.x, a0.y, h, l); *(uint32_t*)&Ah[oA + 0]  = h; *(uint32_t*)&Al[oA + 0]  = l;
            split2(a0.z, a0.w, h, l); *(uint32_t*)&Ah[oA + 2]  = h; *(uint32_t*)&Al[oA + 2]  = l;
            split2(a1.x, a1.y, h, l); *(uint32_t*)&Ah[oA + 4]  = h; *(uint32_t*)&Al[oA + 4]  = l;
            split2(a1.z, a1.w, h, l); *(uint32_t*)&Ah[oA + 6]  = h; *(uint32_t*)&Al[oA + 6]  = l;
            split2(a2.x, a2.y, h, l); *(uint32_t*)&Ah[oA + 8]  = h; *(uint32_t*)&Al[oA + 8]  = l;
            split2(a2.z, a2.w, h, l); *(uint32_t*)&Ah[oA + 10] = h; *(uint32_t*)&Al[oA + 10] = l;
            split2(a3.x, a3.y, h, l); *(uint32_t*)&Ah[oA + 12] = h; *(uint32_t*)&Al[oA + 12] = l;
            split2(a3.z, a3.w, h, l); *(uint32_t*)&Ah[oA + 14] = h; *(uint32_t*)&Al[oA + 14] = l;
            split2(gg0.x, gg0.y, h, l); *(uint32_t*)&Bgh[oB + 0] = h; *(uint32_t*)&Bgl[oB + 0] = l;
            split2(gg0.z, gg0.w, h, l); *(uint32_t*)&Bgh[oB + 2] = h; *(uint32_t*)&Bgl[oB + 2] = l;
            split2(gg1.x, gg1.y, h, l); *(uint32_t*)&Bgh[oB + 4] = h; *(uint32_t*)&Bgl[oB + 4] = l;
            split2(gg1.z, gg1.w, h, l); *(uint32_t*)&Bgh[oB + 6] = h; *(uint32_t*)&Bgl[oB + 6] = l;
            split2(uu0.x, uu0.y, h, l); *(uint32_t*)&Buh[oB + 0] = h; *(uint32_t*)&Bul[oB + 0] = l;
            split2(uu0.z, uu0.w, h, l); *(uint32_t*)&Buh[oB + 2] = h; *(uint32_t*)&Bul[oB + 2] = l;
            split2(uu1.x, uu1.y, h, l); *(uint32_t*)&Buh[oB + 4] = h; *(uint32_t*)&Bul[oB + 4] = l;
            split2(uu1.z, uu1.w, h, l); *(uint32_t*)&Buh[oB + 6] = h; *(uint32_t*)&Bul[oB + 6] = l;
            __syncthreads();
        }
    }

    // ---- epilogue ----
#pragma unroll
    for (int mf = 0; mf < 2; mf++) {
        int rA = base + wm * 32 + mf * 16 + (lane >> 2);
        float wa = g_w[rA], wb = g_w[rA + 8];
#pragma unroll
        for (int nf = 0; nf < 4; nf++) {
            int col = j0 + wn * 32 + nf * 8 + (lane & 3) * 2;
            float o0 = silu_f(accg[mf][nf][0]) * accu[mf][nf][0] * wa;
            float o1 = silu_f(accg[mf][nf][1]) * accu[mf][nf][1] * wa;
            float o2 = silu_f(accg[mf][nf][2]) * accu[mf][nf][2] * wb;
            float o3 = silu_f(accg[mf][nf][3]) * accu[mf][nf][3] * wb;
            uint32_t h, l;
            split2(o0, o1, h, l);
            *(uint32_t*)&g_ih[(size_t)rA * NI + col] = h;
            *(uint32_t*)&g_il[(size_t)rA * NI + col] = l;
            split2(o2, o3, h, l);
            *(uint32_t*)&g_ih[(size_t)(rA + 8) * NI + col] = h;
            *(uint32_t*)&g_il[(size_t)(rA + 8) * NI + col] = l;
        }
    }
}

// ---------------- GEMM2: out[t,:] += inter @ W2[e] ----------------------------
__global__ __launch_bounds__(256)
void k_gemm2(const float* __restrict__ W2, float* __restrict__ out) {
    int tile = blockIdx.y;
    int e = g_tile_e[tile];
    if (e < 0) return;
    int base = g_tile_base[tile];
    int n0 = blockIdx.x * 64;

    __shared__ __align__(16) __nv_bfloat16 Ah[BM * ASTR], Al[BM * ASTR];
    __shared__ __align__(16) __nv_bfloat16 Bh[KC * BSTR], Bl[KC * BSTR];

    int tid = threadIdx.x, lane = tid & 31, wid = tid >> 5;
    int wm = wid & 3, wn = wid >> 2;

    const float* W = W2 + (size_t)e * NI * NH;

    int arow = tid >> 1, akp = (tid & 1) * 16;
    const __nv_bfloat16* ih = g_ih + (size_t)(base + arow) * NI + akp;
    const __nv_bfloat16* il = g_il + (size_t)(base + arow) * NI + akp;
    int bkr = tid >> 3, bc = (tid & 7) * 8;
    const float* wbase = W + (size_t)bkr * NH + n0 + bc;
    int oA = arow * ASTR + akp;
    int oB = bkr * BSTR + bc;

    uint32_t sAh = smem_u32(Ah), sAl = smem_u32(Al);
    uint32_t sBh = smem_u32(Bh), sBl = smem_u32(Bl);

    uint32_t aoff[2], boff[2];
#pragma unroll
    for (int mf = 0; mf < 2; mf++)
        aoff[mf] = (uint32_t)((wm * 32 + mf * 16 + (lane & 15)) * (ASTR * 2) + (lane >> 4) * 16);
#pragma unroll
    for (int nb = 0; nb < 2; nb++)
        boff[nb] = (uint32_t)((lane & 15) * (BSTR * 2) + (wn * 32 + nb * 16 + (lane >> 4) * 8) * 2);

    float acc[2][4][4] = {};
    const int NC = NI / KC;

    // ---- prologue ----
    {
        const uint4* ph = (const uint4*)ih;
        const uint4* pl = (const uint4*)il;
        uint4 vh0 = ph[0], vh1 = ph[1], vl0 = pl[0], vl1 = pl[1];
        float4 b0 = *(const float4*)wbase, b1 = *(const float4*)(wbase + 4);
        *(uint4*)&Ah[oA] = vh0; *(uint4*)&Ah[oA + 8] = vh1;
        *(uint4*)&Al[oA] = vl0; *(uint4*)&Al[oA + 8] = vl1;
        uint32_t h, l;
        split2(b0.x, b0.y, h, l); *(uint32_t*)&Bh[oB + 0] = h; *(uint32_t*)&Bl[oB + 0] = l;
        split2(b0.z, b0.w, h, l); *(uint32_t*)&Bh[oB + 2] = h; *(uint32_t*)&Bl[oB + 2] = l;
        split2(b1.x, b1.y, h, l); *(uint32_t*)&Bh[oB + 4] = h; *(uint32_t*)&Bl[oB + 4] = l;
        split2(b1.z, b1.w, h, l); *(uint32_t*)&Bh[oB + 6] = h; *(uint32_t*)&Bl[oB + 6] = l;
    }
    __syncthreads();

    for (int c = 0; c < NC; c++) {
        uint4 vh0, vh1, vl0, vl1; float4 b0, b1;
        bool more = (c + 1 < NC);
        if (more) {
            int k0 = (c + 1) * KC;
            const uint4* ph = (const uint4*)(ih + k0);
            const uint4* pl = (const uint4*)(il + k0);
            vh0 = ph[0]; vh1 = ph[1]; vl0 = pl[0]; vl1 = pl[1];
            const float* pb = wbase + (size_t)k0 * NH;
            b0 = *(const float4*)pb; b1 = *(const float4*)(pb + 4);
        }
#pragma unroll
        for (int s = 0; s < 2; s++) {
            uint32_t ah[2][4], al[2][4], bb[2][4];
            uint32_t as_ = (uint32_t)(s * 32), bs_ = (uint32_t)(s * 16 * BSTR * 2);
            ldm_x4(ah[0], sAh + aoff[0] + as_);
            ldm_x4(ah[1], sAh + aoff[1] + as_);
            ldm_x4(al[0], sAl + aoff[0] + as_);
            ldm_x4(al[1], sAl + aoff[1] + as_);
            ldm_x4t(bb[0], sBh + boff[0] + bs_);
            ldm_x4t(bb[1], sBh + boff[1] + bs_);
#pragma unroll
            for (int mf = 0; mf < 2; mf++)
#pragma unroll
                for (int nb = 0; nb < 2; nb++)
#pragma unroll
                    for (int f = 0; f < 2; f++) {
                        mma_bf16(acc[mf][nb * 2 + f], ah[mf], &bb[nb][f * 2]);
                        mma_bf16(acc[mf][nb * 2 + f], al[mf], &bb[nb][f * 2]);
                    }
            ldm_x4t(bb[0], sBl + boff[0] + bs_);
            ldm_x4t(bb[1], sBl + boff[1] + bs_);
#pragma unroll
            for (int mf = 0; mf < 2; mf++)
#pragma unroll
                for (int nb = 0; nb < 2; nb++)
#pragma unroll
                    for (int f = 0; f < 2; f++)
                        mma_bf16(acc[mf][nb * 2 + f], ah[mf], &bb[nb][f * 2]);
        }
        __syncthreads();
        if (more) {
            *(uint4*)&Ah[oA] = vh0; *(uint4*)&Ah[oA + 8] = vh1;
            *(uint4*)&Al[oA] = vl0; *(uint4*)&Al[oA + 8] = vl1;
            uint32_t h, l;
            split2(b0.x, b0.y, h, l); *(uint32_t*)&Bh[oB + 0] = h; *(uint32_t*)&Bl[oB + 0] = l;
            split2(b0.z, b0.w, h, l); *(uint32_t*)&Bh[oB + 2] = h; *(uint32_t*)&Bl[oB + 2] = l;
            split2(b1.x, b1.y, h, l); *(uint32_t*)&Bh[oB + 4] = h; *(uint32_t*)&Bl[oB + 4] = l;
            split2(b1.z, b1.w, h, l); *(uint32_t*)&Bh[oB + 6] = h; *(uint32_t*)&Bl[oB + 6] = l;
            __syncthreads();
        }
    }

#pragma unroll
    for (int mf = 0; mf < 2; mf++) {
        int rA = base + wm * 32 + mf * 16 + (lane >> 2);
        int tA = g_tok[rA], tB = g_tok[rA + 8];
#pragma unroll
        for (int nf = 0; nf < 4; nf++) {
            int col = n0 + wn * 32 + nf * 8 + (lane & 3) * 2;
            atomicAdd(&out[(size_t)tA * NH + col],     acc[mf][nf][0]);
            atomicAdd(&out[(size_t)tA * NH + col + 1], acc[mf][nf][1]);
            atomicAdd(&out[(size_t)tB * NH + col],     acc[mf][nf][2]);
            atomicAdd(&out[(size_t)tB * NH + col + 1], acc[mf][nf][3]);
        }
    }
}

// ---------------- launcher ----------------------------------------------------
extern "C" void kernel_launch(void* const* d_in, const int* in_sizes, int n_in,
                              void* d_out, int out_size) {
    const float* x   = (const float*)d_in[0];
    const int*   idx = (const int*)d_in[1];
    const float* w   = (const float*)d_in[2];
    const float* W1  = (const float*)d_in[3];
    const float* W2  = (const float*)d_in[4];
    float* out = (float*)d_out;

    cudaMemsetAsync(out, 0, (size_t)out_size * sizeof(float));

    k_init<<<1, 64>>>(idx);
    k_fill<<<(PADS + 255) / 256, 256>>>();
    k_count<<<TKP / 256, 256>>>(idx);
    k_scan<<<1, 1>>>();
    k_scatter<<<TKP / 256, 256>>>(idx, w);

    dim3 g1(NI / 64, MAXTT);       // 12 x 128
    k_gemm1<<<g1, 256>>>(x, W1);

    dim3 g2(NH / 64, MAXTT);       // 32 x 128
    k_gemm2<<<g2, 256>>>(W2, out);
}